// round 3
// baseline (speedup 1.0000x reference)
#include <cuda_runtime.h>
#include <math.h>

// Problem constants (fixed by setup_inputs)
#define D       512       // feature dim
#define NROWS   4096      // x rows
#define MREFS   65536     // reference points
#define TOPK    16
#define NSLICE  16        // ref slices (merged in kernel 3)

// GEMM tiling
#define BM 128
#define BN 128
#define BK 16

#define INF_F (__int_as_float(0x7f800000))

// Scratch (no allocations allowed -> device globals)
__device__ float g_xn[NROWS * D];                    // normalized x, 8 MB
__device__ float g_slice[NSLICE * NROWS * TOPK];     // per-slice sorted top-16 d^2, 4 MB

// ---------------------------------------------------------------------------
// packed f32x2 helpers (2x FFMA issue rate vs 3-reg FFMA on sm_103a)
// ---------------------------------------------------------------------------
__device__ __forceinline__ void ffma2(unsigned long long& acc,
                                      unsigned long long a,
                                      unsigned long long b) {
    asm("fma.rn.f32x2 %0, %1, %2, %0;" : "+l"(acc) : "l"(a), "l"(b));
}
__device__ __forceinline__ unsigned long long pack2(float x) {
    unsigned long long r;
    unsigned int u = __float_as_uint(x);
    asm("mov.b64 %0, {%1, %1};" : "=l"(r) : "r"(u));
    return r;
}
__device__ __forceinline__ float lo_of(unsigned long long v) {
    return __uint_as_float((unsigned int)(v & 0xffffffffull));
}
__device__ __forceinline__ float hi_of(unsigned long long v) {
    return __uint_as_float((unsigned int)(v >> 32));
}

// ---------------------------------------------------------------------------
// Kernel 1: L2-normalize x rows -> g_xn
// ---------------------------------------------------------------------------
__global__ void normalize_kernel(const float* __restrict__ x) {
    int row = blockIdx.x;
    int tid = threadIdx.x;           // 128 threads
    const float4* xr = reinterpret_cast<const float4*>(x + (size_t)row * D);
    float4 v = xr[tid];              // 128 * 4 = 512 elements
    float ss = v.x * v.x + v.y * v.y + v.z * v.z + v.w * v.w;

    // warp reduce
    #pragma unroll
    for (int o = 16; o > 0; o >>= 1) ss += __shfl_xor_sync(0xffffffffu, ss, o);

    __shared__ float red[4];
    __shared__ float s_inv;
    if ((tid & 31) == 0) red[tid >> 5] = ss;
    __syncthreads();
    if (tid == 0) {
        float tot = red[0] + red[1] + red[2] + red[3];
        s_inv = 1.0f / fmaxf(sqrtf(tot), 1e-12f);
    }
    __syncthreads();
    float inv = s_inv;
    float4 o;
    o.x = v.x * inv; o.y = v.y * inv; o.z = v.z * inv; o.w = v.w * inv;
    reinterpret_cast<float4*>(g_xn + (size_t)row * D)[tid] = o;
}

// ---------------------------------------------------------------------------
// Kernel 2: fused tiled "GEMM" (cos = xn . ref) + running top-16 of d^2 = 2-2cos
// grid: (NROWS/BM, NSLICE), block: 256 threads, 8x8 micro-tile per thread
// ---------------------------------------------------------------------------
__global__ void __launch_bounds__(256, 2)
knn_tile_kernel(const float* __restrict__ refs, int nrows, int mrefs) {
    __shared__ float xs[BK][BM];          // 8 KB
    __shared__ float rs[BK][BN];          // 8 KB
    __shared__ float topd[BM][TOPK + 1];  // padded: kill bank conflicts (~8.7 KB)
    __shared__ float stage[BM][33];       // padded 32-col staging (~16.9 KB)

    const int tid = threadIdx.x;
    const int tc = tid & 15;     // 0..15 -> cols tc*8..tc*8+7
    const int tr = tid >> 4;     // 0..15 -> rows tr*8..tr*8+7
    const int row0 = blockIdx.x * BM;
    const int sliceLen = mrefs / NSLICE;       // 4096
    const int ntiles = sliceLen / BN;          // 32
    const int slice0 = blockIdx.y * sliceLen;

    // init running top-16 (d^2, ascending)
    for (int t = tid; t < BM * TOPK; t += 256) topd[t / TOPK][t % TOPK] = INF_F;
    __syncthreads();

    const int my_chunk = tc >> 2;              // which 32-col chunk this thread stages

    for (int nt = 0; nt < ntiles; ++nt) {
        const int ref0 = slice0 + nt * BN;

        unsigned long long acc[4][8];
        #pragma unroll
        for (int p = 0; p < 4; ++p)
            #pragma unroll
            for (int j = 0; j < 8; ++j) acc[p][j] = 0ull;

        for (int kt = 0; kt < D / BK; ++kt) {
            const int k0 = kt * BK;
            // load x tile (transposed) : xs[k][m]
            {
                int t = tid;
                #pragma unroll
                for (int rep = 0; rep < 2; ++rep) {
                    int m = t & (BM - 1);
                    int kq = t >> 7;  // 0..3
                    float4 v = *reinterpret_cast<const float4*>(
                        &g_xn[(size_t)(row0 + m) * D + k0 + kq * 4]);
                    int kl = kq * 4;
                    xs[kl + 0][m] = v.x; xs[kl + 1][m] = v.y;
                    xs[kl + 2][m] = v.z; xs[kl + 3][m] = v.w;
                    t += 256;
                }
            }
            // load ref tile (transposed) : rs[k][n]
            {
                int t = tid;
                #pragma unroll
                for (int rep = 0; rep < 2; ++rep) {
                    int n = t & (BN - 1);
                    int kq = t >> 7;
                    float4 v = *reinterpret_cast<const float4*>(
                        &refs[(size_t)(ref0 + n) * D + k0 + kq * 4]);
                    int kl = kq * 4;
                    rs[kl + 0][n] = v.x; rs[kl + 1][n] = v.y;
                    rs[kl + 2][n] = v.z; rs[kl + 3][n] = v.w;
                    t += 256;
                }
            }
            __syncthreads();

            #pragma unroll
            for (int k = 0; k < BK; ++k) {
                unsigned long long a2[4];
                #pragma unroll
                for (int p = 0; p < 4; ++p)
                    a2[p] = *reinterpret_cast<const unsigned long long*>(
                        &xs[k][tr * 8 + 2 * p]);
                float4 bl = *reinterpret_cast<const float4*>(&rs[k][tc * 8]);
                float4 bh = *reinterpret_cast<const float4*>(&rs[k][tc * 8 + 4]);
                unsigned long long b2[8];
                b2[0] = pack2(bl.x); b2[1] = pack2(bl.y);
                b2[2] = pack2(bl.z); b2[3] = pack2(bl.w);
                b2[4] = pack2(bh.x); b2[5] = pack2(bh.y);
                b2[6] = pack2(bh.z); b2[7] = pack2(bh.w);
                #pragma unroll
                for (int p = 0; p < 4; ++p)
                    #pragma unroll
                    for (int j = 0; j < 8; ++j) ffma2(acc[p][j], a2[p], b2[j]);
            }
            __syncthreads();
        }

        // top-k update: 4 chunks of 32 columns through the staging buffer
        for (int ch = 0; ch < 4; ++ch) {
            if (ch == my_chunk) {
                const int cbase = (tc & 3) * 8;
                #pragma unroll
                for (int p = 0; p < 4; ++p) {
                    #pragma unroll
                    for (int j = 0; j < 8; ++j) {
                        float c0 = lo_of(acc[p][j]);
                        float c1 = hi_of(acc[p][j]);
                        stage[tr * 8 + 2 * p + 0][cbase + j] = fmaf(-2.0f, c0, 2.0f);
                        stage[tr * 8 + 2 * p + 1][cbase + j] = fmaf(-2.0f, c1, 2.0f);
                    }
                }
            }
            __syncthreads();
            if (tid < BM) {
                const int r = tid;
                float th = topd[r][TOPK - 1];
                for (int j = 0; j < 32; ++j) {
                    float v = stage[r][j];
                    if (v < th) {
                        int p = TOPK - 1;
                        while (p > 0 && topd[r][p - 1] > v) {
                            topd[r][p] = topd[r][p - 1];
                            --p;
                        }
                        topd[r][p] = v;
                        th = topd[r][TOPK - 1];
                    }
                }
            }
            __syncthreads();
        }
    }

    // dump per-slice sorted top-16 d^2
    for (int t = tid; t < BM * TOPK; t += 256) {
        int r = t / TOPK, j = t % TOPK;
        g_slice[((size_t)blockIdx.y * nrows + row0 + r) * TOPK + j] = topd[r][j];
    }
}

// ---------------------------------------------------------------------------
// Kernel 3: merge NSLICE sorted 16-lists per row -> weights
// ---------------------------------------------------------------------------
__global__ void merge_kernel(float* __restrict__ out, int nrows) {
    int r = blockIdx.x * blockDim.x + threadIdx.x;
    if (r >= nrows) return;

    float best[TOPK];
    #pragma unroll
    for (int j = 0; j < TOPK; ++j) best[j] = INF_F;
    float th = INF_F;

    for (int s = 0; s < NSLICE; ++s) {
        const float* lst = &g_slice[((size_t)s * nrows + r) * TOPK];
        for (int j = 0; j < TOPK; ++j) {
            float v = lst[j];
            if (v >= th) break;  // list is sorted ascending
            int p = TOPK - 1;
            while (p > 0 && best[p - 1] > v) { best[p] = best[p - 1]; --p; }
            best[p] = v;
            th = best[TOPK - 1];
        }
    }

    float w[TOPK];
    float sum = 0.0f;
    #pragma unroll
    for (int j = 0; j < TOPK; ++j) {
        float d = sqrtf(fmaxf(best[j], 1e-12f));
        w[j] = expf(-d);
        sum += w[j];
    }
    float inv = 1.0f / fmaxf(sum, 1e-12f);
    #pragma unroll
    for (int j = 0; j < TOPK; ++j) out[(size_t)r * TOPK + j] = w[j] * inv;
}

// ---------------------------------------------------------------------------
extern "C" void kernel_launch(void* const* d_in, const int* in_sizes, int n_in,
                              void* d_out, int out_size) {
    const float* x    = (const float*)d_in[0];
    const float* refs = (const float*)d_in[1];
    float* out        = (float*)d_out;

    int nrows = in_sizes[0] / D;   // 4096
    int mrefs = in_sizes[1] / D;   // 65536

    normalize_kernel<<<nrows, 128>>>(x);
    dim3 g2(nrows / BM, NSLICE);
    knn_tile_kernel<<<g2, 256>>>(refs, nrows, mrefs);
    merge_kernel<<<(nrows + 255) / 256, 256>>>(out, nrows);
}

// round 8
// speedup vs baseline: 7.7407x; 7.7407x over previous
#include <cuda_runtime.h>
#include <cuda_bf16.h>
#include <math.h>
#include <stdint.h>

// Problem constants (fixed by setup_inputs)
#define D       512
#define NROWS   4096
#define MREFS   65536
#define TOPK    16
#define NSLICE  16

// Tiling
#define BM      128
#define BN      128
#define KC      64              // bf16 per k-chunk (128 B rows)
#define NCHUNK  (D / KC)        // 8

#define INF_F (__int_as_float(0x7f800000))

// ---------------------------------------------------------------------------
// Scratch (device globals; no allocations allowed)
// ---------------------------------------------------------------------------
__device__ __nv_bfloat16 g_xh[NROWS * D];              // 4 MB  normalized x (bf16)
__device__ __nv_bfloat16 g_rh[(size_t)MREFS * D];      // 64 MB refs (bf16)
__device__ float g_slice[NSLICE * NROWS * TOPK];       // per-slice sorted top-16 d^2

// ---------------------------------------------------------------------------
// PTX helpers — ONLY family-portable instructions (harness targets compute_103)
// ---------------------------------------------------------------------------
__device__ __forceinline__ uint32_t smem_u32(const void* p) {
    uint32_t a;
    asm("{ .reg .u64 t; cvta.to.shared.u64 t, %1; cvt.u32.u64 %0, t; }"
        : "=r"(a) : "l"(p));
    return a;
}
#define CP_ASYNC16(dst, src) \
    asm volatile("cp.async.cg.shared.global [%0], [%1], 16;" :: "r"(dst), "l"(src))
#define CP_COMMIT()  asm volatile("cp.async.commit_group;" ::: "memory")
#define CP_WAIT(N)   asm volatile("cp.async.wait_group %0;" :: "n"(N) : "memory")

__device__ __forceinline__ void ldsm_x4(uint32_t* r, uint32_t addr) {
    asm volatile("ldmatrix.sync.aligned.m8n8.x4.shared.b16 {%0,%1,%2,%3}, [%4];"
        : "=r"(r[0]), "=r"(r[1]), "=r"(r[2]), "=r"(r[3]) : "r"(addr));
}
__device__ __forceinline__ void mma16816(float* d, const uint32_t* a,
                                         uint32_t b0, uint32_t b1) {
    asm volatile(
        "mma.sync.aligned.m16n8k16.row.col.f32.bf16.bf16.f32 "
        "{%0,%1,%2,%3}, {%4,%5,%6,%7}, {%8,%9}, {%0,%1,%2,%3};"
        : "+f"(d[0]), "+f"(d[1]), "+f"(d[2]), "+f"(d[3])
        : "r"(a[0]), "r"(a[1]), "r"(a[2]), "r"(a[3]), "r"(b0), "r"(b1));
}

// ---------------------------------------------------------------------------
// Kernel A: normalize x rows -> bf16
// ---------------------------------------------------------------------------
__global__ void conv_x_kernel(const float* __restrict__ x) {
    int row = blockIdx.x;
    int tid = threadIdx.x;  // 128
    float4 v = reinterpret_cast<const float4*>(x + (size_t)row * D)[tid];
    float ss = v.x * v.x + v.y * v.y + v.z * v.z + v.w * v.w;
    #pragma unroll
    for (int o = 16; o > 0; o >>= 1) ss += __shfl_xor_sync(0xffffffffu, ss, o);
    __shared__ float red[4];
    __shared__ float s_inv;
    if ((tid & 31) == 0) red[tid >> 5] = ss;
    __syncthreads();
    if (tid == 0) {
        float tot = red[0] + red[1] + red[2] + red[3];
        s_inv = 1.0f / fmaxf(sqrtf(tot), 1e-12f);
    }
    __syncthreads();
    float inv = s_inv;
    __nv_bfloat162 a = __floats2bfloat162_rn(v.x * inv, v.y * inv);
    __nv_bfloat162 b = __floats2bfloat162_rn(v.z * inv, v.w * inv);
    uint2 pk = make_uint2(*(uint32_t*)&a, *(uint32_t*)&b);
    reinterpret_cast<uint2*>(g_xh + (size_t)row * D)[tid] = pk;
}

// ---------------------------------------------------------------------------
// Kernel B: refs fp32 -> bf16 (already L2-normalized)
// ---------------------------------------------------------------------------
__global__ void conv_r_kernel(const float* __restrict__ refs) {
    size_t i = ((size_t)blockIdx.x * blockDim.x + threadIdx.x) * 8;
    float4 a = *reinterpret_cast<const float4*>(refs + i);
    float4 b = *reinterpret_cast<const float4*>(refs + i + 4);
    __nv_bfloat162 p0 = __floats2bfloat162_rn(a.x, a.y);
    __nv_bfloat162 p1 = __floats2bfloat162_rn(a.z, a.w);
    __nv_bfloat162 p2 = __floats2bfloat162_rn(b.x, b.y);
    __nv_bfloat162 p3 = __floats2bfloat162_rn(b.z, b.w);
    uint4 pk = make_uint4(*(uint32_t*)&p0, *(uint32_t*)&p1,
                          *(uint32_t*)&p2, *(uint32_t*)&p3);
    *reinterpret_cast<uint4*>(g_rh + i) = pk;
}

// ---------------------------------------------------------------------------
// Kernel C: bf16 mma.sync GEMM (cos) + fused per-row top-16 of d^2 = 2 - 2 cos
// grid (NROWS/BM, NSLICE), 256 threads (8 warps, 2x4 warp grid, 64x32 per warp)
// ---------------------------------------------------------------------------
#define SM_A      0                       // 2 stages x 16 KB
#define SM_B      32768                   // 2 stages x 16 KB
#define SM_STAGE  65536                   // 128 x 68 floats = 34816 B
#define STG_LD    68
#define SM_TOTAL  (SM_STAGE + BM * STG_LD * 4)

// swizzled smem byte offset for (row, kbyte) in a [128 x 128B] tile
__device__ __forceinline__ uint32_t swz(int row, int kbyte) {
    return (uint32_t)(row * 128 + (kbyte ^ ((row & 7) << 4)));
}

// issue one 128x128B chunk load (1024 x 16B) via cp.async
__device__ __forceinline__ void load_chunk(uint32_t dst_base,
                                           const __nv_bfloat16* src_base, int tid) {
    #pragma unroll
    for (int i = 0; i < 4; ++i) {
        int idx = tid + i * 256;
        int row = idx >> 3, seg = idx & 7;
        uint32_t dst = dst_base + swz(row, seg * 16);
        const void* src = src_base + (size_t)row * D + seg * 8;
        CP_ASYNC16(dst, src);
    }
}

__global__ void __launch_bounds__(256, 2)
knn_mma_kernel(int nrows, int mrefs) {
    extern __shared__ char smem[];
    const uint32_t sb = smem_u32(smem);
    float* stage = reinterpret_cast<float*>(smem + SM_STAGE);

    const int tid  = threadIdx.x;
    const int lane = tid & 31;
    const int wid  = tid >> 5;
    const int wm   = wid >> 2;          // 0..1 -> rows wm*64
    const int wn   = wid & 3;           // 0..3 -> cols wn*32

    const int row0     = blockIdx.x * BM;
    const int sliceLen = mrefs / NSLICE;           // 4096
    const int slice0   = blockIdx.y * sliceLen;
    const int ntiles   = sliceLen / BN;            // 32
    const int NG       = ntiles * NCHUNK;          // 256 chunk-iterations

    const __nv_bfloat16* Abase = g_xh + (size_t)row0 * D;

    // per-thread sorted top-16 (thread r < 128 owns row row0 + r)
    float best[TOPK];
    #pragma unroll
    for (int j = 0; j < TOPK; ++j) best[j] = INF_F;

    // ldmatrix lane addressing (precompute row / kbyte components)
    const int a_row_l = lane & 15;              // + wm*64 + mi*16
    const int a_kb_l  = (lane >> 4) << 4;       // 0 or 16
    const int b_row_l = ((lane >> 4) << 3) + (lane & 7);  // + wn*32 + nip*16
    const int b_kb_l  = ((lane >> 3) & 1) << 4; // 0 or 16

    float acc[4][4][4];
    #pragma unroll
    for (int mi = 0; mi < 4; ++mi)
        #pragma unroll
        for (int nt = 0; nt < 4; ++nt)
            #pragma unroll
            for (int q = 0; q < 4; ++q) acc[mi][nt][q] = 0.0f;

    // prologue: issue chunk 0 into stage 0
    load_chunk(sb + SM_A, Abase, tid);
    load_chunk(sb + SM_B, g_rh + (size_t)slice0 * D, tid);
    CP_COMMIT();

    for (int g = 0; g < NG; ++g) {
        const int t = g >> 3;          // tile
        const int c = g & 7;           // k-chunk
        const int s = g & 1;           // stage

        // issue next chunk into the other stage
        if (g + 1 < NG) {
            const int gn = g + 1;
            const int tn = gn >> 3, cn = gn & 7, sn = gn & 1;
            load_chunk(sb + SM_A + sn * 16384, Abase + cn * KC, tid);
            load_chunk(sb + SM_B + sn * 16384,
                       g_rh + (size_t)(slice0 + tn * BN) * D + cn * KC, tid);
            CP_COMMIT();
            CP_WAIT(1);
        } else {
            CP_WAIT(0);
        }
        __syncthreads();

        // compute chunk: 4 k-steps of m16n8k16
        {
            const uint32_t As = sb + SM_A + s * 16384;
            const uint32_t Bs = sb + SM_B + s * 16384;
            #pragma unroll
            for (int ks = 0; ks < 4; ++ks) {
                uint32_t a[4][4], b[2][4];
                #pragma unroll
                for (int mi = 0; mi < 4; ++mi) {
                    int row = wm * 64 + mi * 16 + a_row_l;
                    ldsm_x4(a[mi], As + swz(row, ks * 32 + a_kb_l));
                }
                #pragma unroll
                for (int nip = 0; nip < 2; ++nip) {
                    int row = wn * 32 + nip * 16 + b_row_l;
                    ldsm_x4(b[nip], Bs + swz(row, ks * 32 + b_kb_l));
                }
                #pragma unroll
                for (int mi = 0; mi < 4; ++mi) {
                    #pragma unroll
                    for (int nt = 0; nt < 4; ++nt)
                        mma16816(acc[mi][nt], a[mi],
                                 b[nt >> 1][(nt & 1) * 2],
                                 b[nt >> 1][(nt & 1) * 2 + 1]);
                }
            }
        }
        __syncthreads();   // stage s free for reuse by load at iteration g+1

        // ---- tile finished? epilogue: d^2 -> stage smem -> per-row top-16 ----
        if (c == NCHUNK - 1) {
            const int g8 = lane >> 2, tig = lane & 3;
            #pragma unroll
            for (int h = 0; h < 2; ++h) {
                if ((wn >> 1) == h) {
                    const int wnl = wn & 1;
                    #pragma unroll
                    for (int mi = 0; mi < 4; ++mi) {
                        #pragma unroll
                        for (int nt = 0; nt < 4; ++nt) {
                            int r = wm * 64 + mi * 16 + g8;
                            int cc = wnl * 32 + nt * 8 + 2 * tig;
                            float2 lo = make_float2(
                                fmaf(-2.0f, acc[mi][nt][0], 2.0f),
                                fmaf(-2.0f, acc[mi][nt][1], 2.0f));
                            float2 hi = make_float2(
                                fmaf(-2.0f, acc[mi][nt][2], 2.0f),
                                fmaf(-2.0f, acc[mi][nt][3], 2.0f));
                            *reinterpret_cast<float2*>(&stage[r * STG_LD + cc]) = lo;
                            *reinterpret_cast<float2*>(&stage[(r + 8) * STG_LD + cc]) = hi;
                        }
                    }
                }
                __syncthreads();
                if (tid < BM) {
                    float th = best[TOPK - 1];
                    #pragma unroll
                    for (int i = 0; i < 16; ++i) {
                        float4 v = *reinterpret_cast<const float4*>(
                            &stage[tid * STG_LD + i * 4]);
                        #pragma unroll
                        for (int e = 0; e < 4; ++e) {
                            float vv = (e == 0) ? v.x : (e == 1) ? v.y
                                       : (e == 2) ? v.z : v.w;
                            if (vv < th) {
                                float cur = vv;
                                #pragma unroll
                                for (int q = 0; q < TOPK; ++q) {
                                    float old = best[q];
                                    best[q] = fminf(old, cur);
                                    cur = fmaxf(old, cur);
                                }
                                th = best[TOPK - 1];
                            }
                        }
                    }
                }
                __syncthreads();
            }
            // reset accumulators for next tile
            #pragma unroll
            for (int mi = 0; mi < 4; ++mi)
                #pragma unroll
                for (int nt = 0; nt < 4; ++nt)
                    #pragma unroll
                    for (int q = 0; q < 4; ++q) acc[mi][nt][q] = 0.0f;
        }
    }

    // dump per-slice sorted top-16
    if (tid < BM) {
        float* dst = &g_slice[((size_t)blockIdx.y * nrows + row0 + tid) * TOPK];
        #pragma unroll
        for (int j = 0; j < TOPK; ++j) dst[j] = best[j];
    }
}

// ---------------------------------------------------------------------------
// Kernel D: merge NSLICE sorted 16-lists per row -> weights
// ---------------------------------------------------------------------------
__global__ void merge_kernel(float* __restrict__ out, int nrows) {
    int r = blockIdx.x * blockDim.x + threadIdx.x;
    if (r >= nrows) return;

    float best[TOPK];
    #pragma unroll
    for (int j = 0; j < TOPK; ++j) best[j] = INF_F;
    float th = INF_F;

    for (int s = 0; s < NSLICE; ++s) {
        const float* lst = &g_slice[((size_t)s * nrows + r) * TOPK];
        for (int j = 0; j < TOPK; ++j) {
            float v = lst[j];
            if (v >= th) break;  // lists are sorted ascending
            int p = TOPK - 1;
            while (p > 0 && best[p - 1] > v) { best[p] = best[p - 1]; --p; }
            best[p] = v;
            th = best[TOPK - 1];
        }
    }

    float w[TOPK];
    float sum = 0.0f;
    #pragma unroll
    for (int j = 0; j < TOPK; ++j) {
        float d = sqrtf(fmaxf(best[j], 1e-12f));
        w[j] = expf(-d);
        sum += w[j];
    }
    float inv = 1.0f / fmaxf(sum, 1e-12f);
    #pragma unroll
    for (int j = 0; j < TOPK; ++j) out[(size_t)r * TOPK + j] = w[j] * inv;
}

// ---------------------------------------------------------------------------
extern "C" void kernel_launch(void* const* d_in, const int* in_sizes, int n_in,
                              void* d_out, int out_size) {
    const float* x    = (const float*)d_in[0];
    const float* refs = (const float*)d_in[1];
    float* out        = (float*)d_out;

    int nrows = in_sizes[0] / D;   // 4096
    int mrefs = in_sizes[1] / D;   // 65536

    cudaFuncSetAttribute(knn_mma_kernel,
                         cudaFuncAttributeMaxDynamicSharedMemorySize, SM_TOTAL);

    conv_x_kernel<<<nrows, 128>>>(x);
    conv_r_kernel<<<(unsigned)(((size_t)mrefs * D) / (256 * 8)), 256>>>(refs);

    dim3 g2(nrows / BM, NSLICE);
    knn_mma_kernel<<<g2, 256, SM_TOTAL>>>(nrows, mrefs);

    merge_kernel<<<(nrows + 255) / 256, 256>>>(out, nrows);
}